// round 9
// baseline (speedup 1.0000x reference)
#include <cuda_runtime.h>
#include <math.h>

#define BATCH 2
#define LSEQ 256
#define CB 64
#define DMODEL 512
#define NHEAD 8
#define HD 64
#define NROWS (BATCH*LSEQ)   // 512
#define PSTR 68              // padded pair row stride (floats)
#define KSPLIT 16
#define KCHUNK (DMODEL/KSPLIT)   // 32

// Static scratch
__device__ float g_part[KSPLIT*NROWS*DMODEL];   // split-K partials (reused by both GEMMs)
__device__ float g_wp[NROWS*DMODEL];
__device__ float g_Wqk[DMODEL*DMODEL];
__device__ float g_bqk[DMODEL];
__device__ float g_Wvo[DMODEL*DMODEL];
__device__ float g_bvo[DMODEL];

// ---------------------------------------------------------------------------
// Prep: build combined weights (tiny GEMMs, ~34 MFLOP total).
// ---------------------------------------------------------------------------
__global__ __launch_bounds__(256) void prep_kernel(
    const float* __restrict__ Wq, const float* __restrict__ bq,
    const float* __restrict__ Wk,
    const float* __restrict__ Wv, const float* __restrict__ bv,
    const float* __restrict__ Wo, const float* __restrict__ bo)
{
    __shared__ float Asm[64*68];
    __shared__ float Bsm[64*68];
    const int bid = blockIdx.x;
    const int tid = threadIdx.x;
    const int tx = tid & 15;
    const int ty = tid >> 4;

    if (bid < 64) {
        const int h = bid >> 3, et = bid & 7, e0 = et * 64;
        #pragma unroll
        for (int p = 0; p < 4; p++) {
            int f = tid + p*256; int e = f >> 4, d4 = f & 15;
            float4 v = *(const float4*)&Wq[(e0+e)*DMODEL + h*64 + d4*4];
            *(float4*)&Asm[e*68 + d4*4] = v;
        }
        #pragma unroll
        for (int p = 0; p < 4; p++) {
            int f = tid + p*256; int c = f >> 4, d4 = f & 15;
            float4 v = *(const float4*)&Wk[c*DMODEL + h*64 + d4*4];
            Bsm[(d4*4+0)*68 + c] = v.x; Bsm[(d4*4+1)*68 + c] = v.y;
            Bsm[(d4*4+2)*68 + c] = v.z; Bsm[(d4*4+3)*68 + c] = v.w;
        }
        __syncthreads();
        float acc[4][4] = {};
        #pragma unroll 8
        for (int d = 0; d < 64; d++) {
            float4 b = *(const float4*)&Bsm[d*68 + tx*4];
            #pragma unroll
            for (int rr = 0; rr < 4; rr++) {
                float a = Asm[(ty*4+rr)*68 + d];
                acc[rr][0] += a*b.x; acc[rr][1] += a*b.y;
                acc[rr][2] += a*b.z; acc[rr][3] += a*b.w;
            }
        }
        #pragma unroll
        for (int rr = 0; rr < 4; rr++) {
            float4 o;
            o.x = acc[rr][0]*0.125f; o.y = acc[rr][1]*0.125f;
            o.z = acc[rr][2]*0.125f; o.w = acc[rr][3]*0.125f;
            *(float4*)&g_Wqk[(e0 + ty*4+rr)*DMODEL + h*64 + tx*4] = o;
        }
        if (et == 0 && tid < 64) {
            float acc2 = 0.f;
            #pragma unroll 8
            for (int d = 0; d < 64; d++) acc2 += bq[h*64+d] * Bsm[d*68 + tid];
            g_bqk[h*64 + tid] = acc2 * 0.125f;
        }
    } else if (bid < 128) {
        const int b2 = bid - 64, h = b2 >> 3, nt = b2 & 7, n0 = nt * 64;
        #pragma unroll
        for (int p = 0; p < 4; p++) {
            int f = tid + p*256; int c = f >> 4, d4 = f & 15;
            float4 v = *(const float4*)&Wv[c*DMODEL + h*64 + d4*4];
            *(float4*)&Asm[c*68 + d4*4] = v;
        }
        #pragma unroll
        for (int p = 0; p < 4; p++) {
            int f = tid + p*256; int d = f >> 4, n4 = f & 15;
            float4 v = *(const float4*)&Wo[(h*64+d)*DMODEL + n0 + n4*4];
            *(float4*)&Bsm[d*68 + n4*4] = v;
        }
        __syncthreads();
        float acc[4][4] = {};
        #pragma unroll 8
        for (int d = 0; d < 64; d++) {
            float4 b = *(const float4*)&Bsm[d*68 + tx*4];
            #pragma unroll
            for (int rr = 0; rr < 4; rr++) {
                float a = Asm[(ty*4+rr)*68 + d];
                acc[rr][0] += a*b.x; acc[rr][1] += a*b.y;
                acc[rr][2] += a*b.z; acc[rr][3] += a*b.w;
            }
        }
        #pragma unroll
        for (int rr = 0; rr < 4; rr++) {
            float4 o;
            o.x = acc[rr][0]; o.y = acc[rr][1]; o.z = acc[rr][2]; o.w = acc[rr][3];
            *(float4*)&g_Wvo[(h*64 + ty*4+rr)*DMODEL + n0 + tx*4] = o;
        }
    } else {
        const int nb = bid - 128, n0 = nb * 64;
        const int n = tid & 63, mg = tid >> 6;
        float acc = 0.f;
        for (int m = mg*128; m < mg*128 + 128; m++)
            acc += bv[m] * Wo[m*DMODEL + n0 + n];
        Asm[mg*64 + n] = acc;
        __syncthreads();
        if (tid < 64) {
            float s = Asm[tid] + Asm[64+tid] + Asm[128+tid] + Asm[192+tid] + bo[n0+tid];
            g_bvo[n0 + tid] = s;
        }
    }
}

// ---------------------------------------------------------------------------
// Split-K GEMM: partial[kz] = A[:, kz*32:(kz+1)*32] @ W[chunk]
// BM=64, BN=64, KCHUNK=32; 128 threads; 8x4/thread; grid (8,8,16)=1024 blocks.
// ---------------------------------------------------------------------------
__global__ __launch_bounds__(128) void gemm_splitk_kernel(
    const float* __restrict__ A, const float* __restrict__ W)
{
    __shared__ float As[32*68];   // [k][m], padded
    __shared__ float Bs[32*64];   // [k][n]
    const int bx = blockIdx.x;    // n tile (64)
    const int by = blockIdx.y;    // m tile (64)
    const int kz = blockIdx.z;
    const int tid = threadIdx.x;
    const int tx = tid & 15;      // 4 cols
    const int ty = tid >> 4;      // 8 rows (8 groups)
    const int k0 = kz * KCHUNK;

    // Load A chunk 64x32, store transposed As[k][m]
    {
        const int am = tid >> 3;     // 0..15
        const int ak4 = tid & 7;     // 0..7  (k = ak4*4 .. +3)
        #pragma unroll
        for (int p = 0; p < 4; p++) {
            int m = am + p*16;
            float4 v = *(const float4*)&A[(by*64 + m)*DMODEL + k0 + ak4*4];
            As[(ak4*4+0)*68 + m] = v.x;
            As[(ak4*4+1)*68 + m] = v.y;
            As[(ak4*4+2)*68 + m] = v.z;
            As[(ak4*4+3)*68 + m] = v.w;
        }
    }
    // Load B chunk 32x64
    {
        const int bk = tid >> 4;     // 0..7
        const int bn4 = tid & 15;
        #pragma unroll
        for (int p = 0; p < 4; p++) {
            int k = bk + p*8;
            float4 v = *(const float4*)&W[(k0 + k)*DMODEL + bx*64 + bn4*4];
            *(float4*)&Bs[k*64 + bn4*4] = v;
        }
    }
    __syncthreads();

    float acc[8][4] = {};
    #pragma unroll 16
    for (int k = 0; k < KCHUNK; k++) {
        float4 b  = *(const float4*)&Bs[k*64 + tx*4];
        float4 a0 = *(const float4*)&As[k*68 + ty*8];
        float4 a1 = *(const float4*)&As[k*68 + ty*8 + 4];
        acc[0][0] += a0.x*b.x; acc[0][1] += a0.x*b.y; acc[0][2] += a0.x*b.z; acc[0][3] += a0.x*b.w;
        acc[1][0] += a0.y*b.x; acc[1][1] += a0.y*b.y; acc[1][2] += a0.y*b.z; acc[1][3] += a0.y*b.w;
        acc[2][0] += a0.z*b.x; acc[2][1] += a0.z*b.y; acc[2][2] += a0.z*b.z; acc[2][3] += a0.z*b.w;
        acc[3][0] += a0.w*b.x; acc[3][1] += a0.w*b.y; acc[3][2] += a0.w*b.z; acc[3][3] += a0.w*b.w;
        acc[4][0] += a1.x*b.x; acc[4][1] += a1.x*b.y; acc[4][2] += a1.x*b.z; acc[4][3] += a1.x*b.w;
        acc[5][0] += a1.y*b.x; acc[5][1] += a1.y*b.y; acc[5][2] += a1.y*b.z; acc[5][3] += a1.y*b.w;
        acc[6][0] += a1.z*b.x; acc[6][1] += a1.z*b.y; acc[6][2] += a1.z*b.z; acc[6][3] += a1.z*b.w;
        acc[7][0] += a1.w*b.x; acc[7][1] += a1.w*b.y; acc[7][2] += a1.w*b.z; acc[7][3] += a1.w*b.w;
    }

    float* P = &g_part[(size_t)kz * NROWS * DMODEL];
    const int r0 = by*64 + ty*8;
    const int c0 = bx*64 + tx*4;
    #pragma unroll
    for (int rr = 0; rr < 8; rr++)
        *(float4*)&P[(r0+rr)*DMODEL + c0] = make_float4(acc[rr][0], acc[rr][1], acc[rr][2], acc[rr][3]);
}

// ---------------------------------------------------------------------------
// Attention per row. Same structure as round-8 (verified) EXCEPT: wp partials
// folded once via shfl_xor(16) (same c4, adjacent jg) -> red halved to 16KB,
// SMEM/block 112.6KB -> 96.25KB -> 2 blocks/SM.
// ---------------------------------------------------------------------------
__global__ __launch_bounds__(256) void attn_kernel(const float* __restrict__ pair)
{
    extern __shared__ float sm[];
    float* pairS = sm;                       // 256*68 = 17408 f
    float* qk_sm = sm + 256*PSTR;            // 512 f
    float* w_sm  = qk_sm + DMODEL;           // 2048 f ([j][h])
    float* red   = w_sm + 2048;              // 8*8*16*4 = 4096 f (16 KB)

    const int row  = blockIdx.x;
    const int tid  = threadIdx.x;
    const int lane = tid & 31;
    const int warp = tid >> 5;

    // Load pair row tile (256 x 64) into padded SMEM
    const float4* pg = (const float4*)(pair + (size_t)row * (LSEQ*CB));
    #pragma unroll
    for (int it = 0; it < 16; it++) {
        int f = tid + it*256;
        int j = f >> 4, c4 = f & 15;
        float4 v = pg[f];
        *(float4*)&pairS[j*PSTR + c4*4] = v;
    }
    // Reduce split-K partials for this row's qk vector
    {
        float2 acc = *(const float2*)&g_bqk[tid*2];
        #pragma unroll
        for (int kz = 0; kz < KSPLIT; kz++) {
            float2 v = *(const float2*)&g_part[((size_t)kz*NROWS + row)*DMODEL + tid*2];
            acc.x += v.x; acc.y += v.y;
        }
        *(float2*)&qk_sm[tid*2] = acc;
    }
    __syncthreads();

    // Scores for this thread's j across all heads
    float s[NHEAD] = {};
    {
        const float4* prow = (const float4*)&pairS[tid*PSTR];
        #pragma unroll
        for (int c4 = 0; c4 < 16; c4++) {
            float4 p = prow[c4];
            #pragma unroll
            for (int h = 0; h < NHEAD; h++) {
                float4 q = *(const float4*)&qk_sm[h*64 + c4*4];
                s[h] += p.x*q.x + p.y*q.y + p.z*q.z + p.w*q.w;
            }
        }
    }

    // Softmax over j (per head)
    #pragma unroll
    for (int h = 0; h < NHEAD; h++) {
        float v = s[h];
        #pragma unroll
        for (int o = 16; o; o >>= 1) v = fmaxf(v, __shfl_xor_sync(0xffffffffu, v, o));
        if (lane == 0) red[warp*NHEAD + h] = v;
    }
    __syncthreads();
    float m[NHEAD];
    #pragma unroll
    for (int h = 0; h < NHEAD; h++) {
        float v = red[h];
        #pragma unroll
        for (int w2 = 1; w2 < 8; w2++) v = fmaxf(v, red[w2*NHEAD + h]);
        m[h] = v;
    }
    __syncthreads();

    float e[NHEAD], Zi[NHEAD];
    #pragma unroll
    for (int h = 0; h < NHEAD; h++) {
        e[h] = __expf(s[h] - m[h]);
        float v = e[h];
        #pragma unroll
        for (int o = 16; o; o >>= 1) v += __shfl_xor_sync(0xffffffffu, v, o);
        if (lane == 0) red[warp*NHEAD + h] = v;
    }
    __syncthreads();
    #pragma unroll
    for (int h = 0; h < NHEAD; h++) {
        float v = 0.f;
        #pragma unroll
        for (int w2 = 0; w2 < 8; w2++) v += red[w2*NHEAD + h];
        Zi[h] = 1.0f / v;
    }
    __syncthreads();

    // Store normalized weights transposed: w_sm[j][h]
    {
        float4 wlo = make_float4(e[0]*Zi[0], e[1]*Zi[1], e[2]*Zi[2], e[3]*Zi[3]);
        float4 whi = make_float4(e[4]*Zi[4], e[5]*Zi[5], e[6]*Zi[6], e[7]*Zi[7]);
        *(float4*)&w_sm[tid*8 + 0] = wlo;
        *(float4*)&w_sm[tid*8 + 4] = whi;
    }
    __syncthreads();

    // wp partials: thread = (c4, jgroup); all 8 heads in registers
    {
        const int c4 = tid & 15, jg = tid >> 4;
        float4 acc[NHEAD];
        #pragma unroll
        for (int h = 0; h < NHEAD; h++) acc[h] = make_float4(0.f,0.f,0.f,0.f);
        #pragma unroll 4
        for (int jj = 0; jj < 16; jj++) {
            int j = jg*16 + jj;
            float4 p  = *(const float4*)&pairS[j*PSTR + c4*4];
            float4 wA = *(const float4*)&w_sm[j*8];
            float4 wB = *(const float4*)&w_sm[j*8 + 4];
            acc[0].x += wA.x*p.x; acc[0].y += wA.x*p.y; acc[0].z += wA.x*p.z; acc[0].w += wA.x*p.w;
            acc[1].x += wA.y*p.x; acc[1].y += wA.y*p.y; acc[1].z += wA.y*p.z; acc[1].w += wA.y*p.w;
            acc[2].x += wA.z*p.x; acc[2].y += wA.z*p.y; acc[2].z += wA.z*p.z; acc[2].w += wA.z*p.w;
            acc[3].x += wA.w*p.x; acc[3].y += wA.w*p.y; acc[3].z += wA.w*p.z; acc[3].w += wA.w*p.w;
            acc[4].x += wB.x*p.x; acc[4].y += wB.x*p.y; acc[4].z += wB.x*p.z; acc[4].w += wB.x*p.w;
            acc[5].x += wB.y*p.x; acc[5].y += wB.y*p.y; acc[5].z += wB.y*p.z; acc[5].w += wB.y*p.w;
            acc[6].x += wB.z*p.x; acc[6].y += wB.z*p.y; acc[6].z += wB.z*p.z; acc[6].w += wB.z*p.w;
            acc[7].x += wB.w*p.x; acc[7].y += wB.w*p.y; acc[7].z += wB.w*p.z; acc[7].w += wB.w*p.w;
        }
        // Fold adjacent j-groups: lane l and l^16 share c4, differ in jg parity.
        #pragma unroll
        for (int h = 0; h < NHEAD; h++) {
            acc[h].x += __shfl_xor_sync(0xffffffffu, acc[h].x, 16);
            acc[h].y += __shfl_xor_sync(0xffffffffu, acc[h].y, 16);
            acc[h].z += __shfl_xor_sync(0xffffffffu, acc[h].z, 16);
            acc[h].w += __shfl_xor_sync(0xffffffffu, acc[h].w, 16);
        }
        if ((jg & 1) == 0) {
            const int jg2 = jg >> 1;   // 0..7
            #pragma unroll
            for (int h = 0; h < NHEAD; h++)
                *(float4*)&red[((jg2*NHEAD + h)*16 + c4)*4] = acc[h];
        }
    }
    __syncthreads();

    // Final reduce over 8 folded jgroups -> g_wp
    if (tid < 128) {
        const int h = tid >> 4, c4 = tid & 15;
        float4 sum = make_float4(0.f,0.f,0.f,0.f);
        #pragma unroll
        for (int jg2 = 0; jg2 < 8; jg2++) {
            float4 v = *(const float4*)&red[((jg2*NHEAD + h)*16 + c4)*4];
            sum.x += v.x; sum.y += v.y; sum.z += v.z; sum.w += v.w;
        }
        *(float4*)&g_wp[row*DMODEL + h*64 + c4*4] = sum;
    }
}

// ---------------------------------------------------------------------------
// LayerNorm(sum_kz part + bvo + x) * gamma + beta -> out.
// ---------------------------------------------------------------------------
__global__ __launch_bounds__(128) void ln_kernel(
    const float* __restrict__ x, const float* __restrict__ gamma,
    const float* __restrict__ beta, float* __restrict__ out)
{
    __shared__ float rs[8];
    const int row = blockIdx.x;
    const int tid = threadIdx.x;
    const int lane = tid & 31, warp = tid >> 5;

    float4 x4 = *(const float4*)&x[row*DMODEL + tid*4];
    float4 b4v = *(const float4*)&g_bvo[tid*4];
    float y0 = x4.x + b4v.x, y1 = x4.y + b4v.y, y2 = x4.z + b4v.z, y3 = x4.w + b4v.w;
    #pragma unroll
    for (int kz = 0; kz < KSPLIT; kz++) {
        float4 p4 = *(const float4*)&g_part[((size_t)kz*NROWS + row)*DMODEL + tid*4];
        y0 += p4.x; y1 += p4.y; y2 += p4.z; y3 += p4.w;
    }

    float sum = y0 + y1 + y2 + y3;
    float sq  = y0*y0 + y1*y1 + y2*y2 + y3*y3;
    #pragma unroll
    for (int o = 16; o; o >>= 1) {
        sum += __shfl_xor_sync(0xffffffffu, sum, o);
        sq  += __shfl_xor_sync(0xffffffffu, sq,  o);
    }
    if (lane == 0) { rs[warp] = sum; rs[4 + warp] = sq; }
    __syncthreads();
    float ts = rs[0] + rs[1] + rs[2] + rs[3];
    float tq = rs[4] + rs[5] + rs[6] + rs[7];
    float mu  = ts * (1.0f/DMODEL);
    float var = tq * (1.0f/DMODEL) - mu*mu;
    float r = rsqrtf(var + 1e-5f);

    float4 g4 = *(const float4*)&gamma[tid*4];
    float4 b4 = *(const float4*)&beta[tid*4];
    float4 o_;
    o_.x = (y0 - mu)*r*g4.x + b4.x;
    o_.y = (y1 - mu)*r*g4.y + b4.y;
    o_.z = (y2 - mu)*r*g4.z + b4.z;
    o_.w = (y3 - mu)*r*g4.w + b4.w;
    *(float4*)&out[row*DMODEL + tid*4] = o_;
}

// ---------------------------------------------------------------------------
extern "C" void kernel_launch(void* const* d_in, const int* in_sizes, int n_in,
                              void* d_out, int out_size)
{
    const float* x     = (const float*)d_in[0];
    const float* pair  = (const float*)d_in[1];
    const float* Wq    = (const float*)d_in[2];
    const float* bq    = (const float*)d_in[3];
    const float* Wk    = (const float*)d_in[4];
    // bk (d_in[5]) is softmax-invariant (per-(row,h) constant), dropped
    const float* Wv    = (const float*)d_in[6];
    const float* bv    = (const float*)d_in[7];
    const float* Wo    = (const float*)d_in[8];
    const float* bo    = (const float*)d_in[9];
    const float* gamma = (const float*)d_in[10];
    const float* beta  = (const float*)d_in[11];
    float* out = (float*)d_out;

    float *pWP, *pWqk, *pWvo;
    cudaGetSymbolAddress((void**)&pWP,  g_wp);
    cudaGetSymbolAddress((void**)&pWqk, g_Wqk);
    cudaGetSymbolAddress((void**)&pWvo, g_Wvo);

    const int ATTN_SMEM = (256*PSTR + DMODEL + 2048 + 4096) * 4;  // 96256 B
    cudaFuncSetAttribute(attn_kernel, cudaFuncAttributeMaxDynamicSharedMemorySize, ATTN_SMEM);

    dim3 ggrid(DMODEL/64, NROWS/64, KSPLIT);   // (8,8,16) = 1024 blocks

    prep_kernel<<<136, 256>>>(Wq, bq, Wk, Wv, bv, Wo, bo);
    gemm_splitk_kernel<<<ggrid, 128>>>(x, pWqk);            // qk partials
    attn_kernel<<<NROWS, 256, ATTN_SMEM>>>(pair);           // reduce + softmax + wp
    gemm_splitk_kernel<<<ggrid, 128>>>(pWP, pWvo);          // o partials
    ln_kernel<<<NROWS, 128>>>(x, gamma, beta, out);         // reduce + LN(o + x)
}